// round 1
// baseline (speedup 1.0000x reference)
#include <cuda_runtime.h>

// Problem constants (fixed shapes from reference)
#define BB 8
#define SE 2048
#define SD 2048
#define DD 1024

// Scratch: scores / probabilities [B, SE, SD] fp32 = 134 MB
__device__ float g_scores[(size_t)BB * SE * SD];

// ---------------------------------------------------------------------------
// GEMM1: S[b,e,t] = sum_d enc[b,e,d] * dec[b,t,d]
// A = enc [SE, DD] row-major (K fast), B = dec [SD, DD] row-major (K fast)
// 128x128 tile, BK=16, 256 threads, 8x8 micro-tile
// ---------------------------------------------------------------------------
__global__ __launch_bounds__(256, 2)
void gemm_scores(const float* __restrict__ enc, const float* __restrict__ dec) {
    __shared__ float As[16][128];
    __shared__ float Bs[16][128];

    const int b    = blockIdx.z;
    const int row0 = blockIdx.y * 128;   // e
    const int col0 = blockIdx.x * 128;   // t

    const float* A  = enc + (size_t)b * SE * DD;
    const float* Bm = dec + (size_t)b * SD * DD;
    float*       C  = g_scores + (size_t)b * SE * SD;

    const int tid = threadIdx.x;
    const int tx  = tid & 15;        // 0..15 -> N
    const int ty  = tid >> 4;        // 0..15 -> M

    // load mapping: 128 rows x 16 k per tile = 512 float4; 256 thr x 2
    const int lr = tid >> 2;         // 0..63
    const int lk = (tid & 3) * 4;    // 0,4,8,12

    float acc[8][8];
    #pragma unroll
    for (int i = 0; i < 8; i++)
        #pragma unroll
        for (int j = 0; j < 8; j++) acc[i][j] = 0.f;

    for (int k0 = 0; k0 < DD; k0 += 16) {
        #pragma unroll
        for (int h = 0; h < 2; h++) {
            const int r = lr + h * 64;
            float4 va = *(const float4*)&A[(size_t)(row0 + r) * DD + k0 + lk];
            As[lk + 0][r] = va.x; As[lk + 1][r] = va.y;
            As[lk + 2][r] = va.z; As[lk + 3][r] = va.w;
            float4 vb = *(const float4*)&Bm[(size_t)(col0 + r) * DD + k0 + lk];
            Bs[lk + 0][r] = vb.x; Bs[lk + 1][r] = vb.y;
            Bs[lk + 2][r] = vb.z; Bs[lk + 3][r] = vb.w;
        }
        __syncthreads();

        #pragma unroll
        for (int k = 0; k < 16; k++) {
            float ra[8], rb[8];
            *(float4*)&ra[0] = *(const float4*)&As[k][ty * 8];
            *(float4*)&ra[4] = *(const float4*)&As[k][ty * 8 + 4];
            *(float4*)&rb[0] = *(const float4*)&Bs[k][tx * 8];
            *(float4*)&rb[4] = *(const float4*)&Bs[k][tx * 8 + 4];
            #pragma unroll
            for (int i = 0; i < 8; i++)
                #pragma unroll
                for (int j = 0; j < 8; j++)
                    acc[i][j] += ra[i] * rb[j];
        }
        __syncthreads();
    }

    #pragma unroll
    for (int i = 0; i < 8; i++) {
        float* crow = &C[(size_t)(row0 + ty * 8 + i) * SD + col0 + tx * 8];
        #pragma unroll
        for (int j = 0; j < 8; j += 4) {
            float4 v = make_float4(acc[i][j], acc[i][j+1], acc[i][j+2], acc[i][j+3]);
            *(float4*)&crow[j] = v;
        }
    }
}

// ---------------------------------------------------------------------------
// Softmax over the last axis (t, length SD) for each (b,e) row, in place.
// One block per row, 256 threads x 8 elements.
// ---------------------------------------------------------------------------
__global__ __launch_bounds__(256)
void softmax_rows() {
    __shared__ float red[8];
    const size_t row = blockIdx.x;
    float* p = g_scores + row * SD;
    const int tid  = threadIdx.x;
    const int lane = tid & 31;
    const int wid  = tid >> 5;

    float4 v0 = *(const float4*)&p[tid * 4];
    float4 v1 = *(const float4*)&p[1024 + tid * 4];

    // --- max reduce ---
    float m = fmaxf(fmaxf(fmaxf(v0.x, v0.y), fmaxf(v0.z, v0.w)),
                    fmaxf(fmaxf(v1.x, v1.y), fmaxf(v1.z, v1.w)));
    #pragma unroll
    for (int o = 16; o > 0; o >>= 1) m = fmaxf(m, __shfl_xor_sync(0xffffffffu, m, o));
    if (lane == 0) red[wid] = m;
    __syncthreads();
    m = red[lane & 7];
    #pragma unroll
    for (int o = 4; o > 0; o >>= 1) m = fmaxf(m, __shfl_xor_sync(0xffffffffu, m, o));
    __syncthreads();

    // --- exp + sum ---
    v0.x = __expf(v0.x - m); v0.y = __expf(v0.y - m);
    v0.z = __expf(v0.z - m); v0.w = __expf(v0.w - m);
    v1.x = __expf(v1.x - m); v1.y = __expf(v1.y - m);
    v1.z = __expf(v1.z - m); v1.w = __expf(v1.w - m);

    float s = (v0.x + v0.y) + (v0.z + v0.w) + (v1.x + v1.y) + (v1.z + v1.w);
    #pragma unroll
    for (int o = 16; o > 0; o >>= 1) s += __shfl_xor_sync(0xffffffffu, s, o);
    if (lane == 0) red[wid] = s;
    __syncthreads();
    s = red[lane & 7];
    #pragma unroll
    for (int o = 4; o > 0; o >>= 1) s += __shfl_xor_sync(0xffffffffu, s, o);

    const float inv = 1.0f / s;
    v0.x *= inv; v0.y *= inv; v0.z *= inv; v0.w *= inv;
    v1.x *= inv; v1.y *= inv; v1.z *= inv; v1.w *= inv;
    *(float4*)&p[tid * 4]        = v0;
    *(float4*)&p[1024 + tid * 4] = v1;
}

// ---------------------------------------------------------------------------
// GEMM2: out[b,t,d] = sum_e P[b,e,t] * enc[b,e,d]
// A' = P with K(=e) strided, M(=t) fast; B' = enc with K(=e) strided, N(=d) fast.
// Both operands load directly into k-major smem (coalesced, no transpose).
// ---------------------------------------------------------------------------
__global__ __launch_bounds__(256, 2)
void gemm_context(const float* __restrict__ enc, float* __restrict__ out) {
    __shared__ float As[16][128];
    __shared__ float Bs[16][128];

    const int b    = blockIdx.z;
    const int row0 = blockIdx.y * 128;   // t
    const int col0 = blockIdx.x * 128;   // d

    const float* P  = g_scores + (size_t)b * SE * SD;  // [e][t]
    const float* Bm = enc + (size_t)b * SE * DD;       // [e][d]
    float*       C  = out + (size_t)b * SD * DD;

    const int tid = threadIdx.x;
    const int tx  = tid & 15;
    const int ty  = tid >> 4;

    // load mapping: 16 k-rows x 128 cols = 512 float4; kr = id/32, c = id%32
    float acc[8][8];
    #pragma unroll
    for (int i = 0; i < 8; i++)
        #pragma unroll
        for (int j = 0; j < 8; j++) acc[i][j] = 0.f;

    for (int k0 = 0; k0 < SE; k0 += 16) {
        #pragma unroll
        for (int h = 0; h < 2; h++) {
            const int id = tid + h * 256;
            const int kr = id >> 5;          // 0..15
            const int c  = (id & 31) * 4;    // 0..124
            *(float4*)&As[kr][c] = *(const float4*)&P [(size_t)(k0 + kr) * SD + row0 + c];
            *(float4*)&Bs[kr][c] = *(const float4*)&Bm[(size_t)(k0 + kr) * DD + col0 + c];
        }
        __syncthreads();

        #pragma unroll
        for (int k = 0; k < 16; k++) {
            float ra[8], rb[8];
            *(float4*)&ra[0] = *(const float4*)&As[k][ty * 8];
            *(float4*)&ra[4] = *(const float4*)&As[k][ty * 8 + 4];
            *(float4*)&rb[0] = *(const float4*)&Bs[k][tx * 8];
            *(float4*)&rb[4] = *(const float4*)&Bs[k][tx * 8 + 4];
            #pragma unroll
            for (int i = 0; i < 8; i++)
                #pragma unroll
                for (int j = 0; j < 8; j++)
                    acc[i][j] += ra[i] * rb[j];
        }
        __syncthreads();
    }

    #pragma unroll
    for (int i = 0; i < 8; i++) {
        float* crow = &C[(size_t)(row0 + ty * 8 + i) * DD + col0 + tx * 8];
        #pragma unroll
        for (int j = 0; j < 8; j += 4) {
            float4 v = make_float4(acc[i][j], acc[i][j+1], acc[i][j+2], acc[i][j+3]);
            *(float4*)&crow[j] = v;
        }
    }
}

// ---------------------------------------------------------------------------
extern "C" void kernel_launch(void* const* d_in, const int* in_sizes, int n_in,
                              void* d_out, int out_size) {
    const float* enc = (const float*)d_in[0];
    const float* dec = (const float*)d_in[1];
    float* out = (float*)d_out;

    {
        dim3 grid(SD / 128, SE / 128, BB);
        gemm_scores<<<grid, 256>>>(enc, dec);
    }
    {
        dim3 grid((unsigned)((size_t)BB * SE), 1, 1);
        softmax_rows<<<grid, 256>>>();
    }
    {
        dim3 grid(DD / 128, SD / 128, BB);
        gemm_context<<<grid, 256>>>(enc, out);
    }
}

// round 12
// speedup vs baseline: 2.3997x; 2.3997x over previous
#include <cuda_runtime.h>
#include <cuda_bf16.h>
#include <cstdint>
#include <cstddef>

#define BB 8
#define TT 2048      // S_dec
#define EE 2048      // S_enc
#define DDIM 1024    // D

// ---------------- scratch (static device arrays; no allocation) ------------
__device__ float g_scores[(size_t)BB * TT * EE];                 // [b][t][e] fp32
__device__ __nv_bfloat16 g_encH[(size_t)BB * EE * DDIM];
__device__ __nv_bfloat16 g_encL[(size_t)BB * EE * DDIM];
__device__ __nv_bfloat16 g_decH[(size_t)BB * TT * DDIM];
__device__ __nv_bfloat16 g_decL[(size_t)BB * TT * DDIM];
__device__ __nv_bfloat16 g_encTH[(size_t)BB * DDIM * EE];        // [b][d][e]
__device__ __nv_bfloat16 g_encTL[(size_t)BB * DDIM * EE];
__device__ __nv_bfloat16 g_ptH[(size_t)BB * TT * EE];            // P^T [b][t][e]
__device__ __nv_bfloat16 g_ptL[(size_t)BB * TT * EE];
#define NSEG 4
__device__ float g_mpart[NSEG * BB * EE];
__device__ float g_spart[NSEG * BB * EE];
__device__ float g_colM[BB * EE];
__device__ float g_colIS[BB * EE];

// ---------------- helpers ---------------------------------------------------
__device__ __forceinline__ uint32_t smem_u32(const void* p) {
    uint32_t a;
    asm("{ .reg .u64 t; cvta.to.shared.u64 t, %1; cvt.u32.u64 %0, t; }"
        : "=r"(a) : "l"(p));
    return a;
}
__device__ __forceinline__ void cp_async16(uint32_t s, const void* g) {
    asm volatile("cp.async.cg.shared.global [%0], [%1], 16;" :: "r"(s), "l"(g) : "memory");
}
__device__ __forceinline__ void cp_commit() {
    asm volatile("cp.async.commit_group;" ::: "memory");
}
__device__ __forceinline__ void cp_wait1() { asm volatile("cp.async.wait_group 1;" ::: "memory"); }
__device__ __forceinline__ void cp_wait0() { asm volatile("cp.async.wait_group 0;" ::: "memory"); }

__device__ __forceinline__ void ldsm_x4(uint32_t& r0, uint32_t& r1, uint32_t& r2, uint32_t& r3,
                                        uint32_t addr) {
    asm volatile("ldmatrix.sync.aligned.m8n8.x4.shared.b16 {%0,%1,%2,%3}, [%4];"
        : "=r"(r0), "=r"(r1), "=r"(r2), "=r"(r3) : "r"(addr));
}
__device__ __forceinline__ void mma16816(float& d0, float& d1, float& d2, float& d3,
                                         uint32_t a0, uint32_t a1, uint32_t a2, uint32_t a3,
                                         uint32_t b0, uint32_t b1) {
    asm volatile("mma.sync.aligned.m16n8k16.row.col.f32.bf16.bf16.f32 "
                 "{%0,%1,%2,%3}, {%4,%5,%6,%7}, {%8,%9}, {%0,%1,%2,%3};"
                 : "+f"(d0), "+f"(d1), "+f"(d2), "+f"(d3)
                 : "r"(a0), "r"(a1), "r"(a2), "r"(a3), "r"(b0), "r"(b1));
}

#define SW128(o) ((o) ^ (((o) >> 3) & 0x70))
#define TILE_BYTES 16384                   // 128 rows x 128B (64 bf16)
#define STAGE_BYTES (4 * TILE_BYTES)       // Ah, Al, Bh, Bl
#define NSTAGE 3
#define GEMM_SMEM (1024 + NSTAGE * STAGE_BYTES)

// load one 64-K-wide stage: 4 operand tiles of 128 rows x 64 bf16
__device__ __forceinline__ void load_stage(uint32_t db, int stage,
    const __nv_bfloat16* pAh, const __nv_bfloat16* pAl,
    const __nv_bfloat16* pBh, const __nv_bfloat16* pBl,
    int k0, int K, int tid)
{
    const __nv_bfloat16* srcs[4] = { pAh + k0, pAl + k0, pBh + k0, pBl + k0 };
    uint32_t sbase = db + stage * STAGE_BYTES;
    #pragma unroll
    for (int tt = 0; tt < 4; tt++) {
        const __nv_bfloat16* s = srcs[tt];
        uint32_t tb = sbase + tt * TILE_BYTES;
        #pragma unroll
        for (int ii = 0; ii < 4; ii++) {
            int i = tid + ii * 256;
            int r = i >> 3, c = i & 7;
            cp_async16(tb + SW128(r * 128 + c * 16), s + (size_t)r * K + c * 8);
        }
    }
    cp_commit();
}

// ---------------- GEMM: C[M,N] = 3-term-split A[M,K] * B[N,K]^T -------------
__global__ __launch_bounds__(256, 1)
void gemm_bf16x3(float* __restrict__ outPtr, int which)
{
    const __nv_bfloat16 *aH, *aL, *bH, *bL;
    float* C;
    int M, N, K;
    if (which == 0) {  // scores^T: C[t][e] = sum_d dec[t,d] * enc[e,d]
        aH = g_decH; aL = g_decL; bH = g_encH; bL = g_encL;
        C = g_scores; M = TT; N = EE; K = DDIM;
    } else {           // out[t][d] = sum_e Pt[t,e] * encT[d,e]
        aH = g_ptH; aL = g_ptL; bH = g_encTH; bL = g_encTL;
        C = outPtr; M = TT; N = DDIM; K = EE;
    }

    extern __shared__ char dsm[];
    const uint32_t db = (smem_u32(dsm) + 1023u) & ~1023u;

    const int tid  = threadIdx.x;
    const int wid  = tid >> 5;
    const int lane = tid & 31;
    const int b    = blockIdx.z;
    const int nc0  = blockIdx.x * 128;
    const int mr0  = blockIdx.y * 128;

    const int wm = wid & 1;          // 2 warps in M
    const int wn = wid >> 1;         // 4 warps in N
    const int wmr = wm * 64;         // warp row offset in tile
    const int wnr = wn * 32;         // warp col offset in tile

    // ldmatrix lane addressing: sub = lane>>3
    const int sub = lane >> 3;
    const int lr  = ((sub & 1) << 3) + (lane & 7);  // row within 16-row block
    const int lc  = sub >> 1;                        // kchunk (16B) within k16

    const __nv_bfloat16* pAh = aH + (size_t)b * M * K + (size_t)mr0 * K;
    const __nv_bfloat16* pAl = aL + (size_t)b * M * K + (size_t)mr0 * K;
    const __nv_bfloat16* pBh = bH + (size_t)b * N * K + (size_t)nc0 * K;
    const __nv_bfloat16* pBl = bL + (size_t)b * N * K + (size_t)nc0 * K;

    float acc[4][4][4];
    #pragma unroll
    for (int i = 0; i < 4; i++)
        #pragma unroll
        for (int j = 0; j < 4; j++) {
            acc[i][j][0] = 0.f; acc[i][j][1] = 0.f;
            acc[i][j][2] = 0.f; acc[i][j][3] = 0.f;
        }

    const int NC = K / 64;
    load_stage(db, 0, pAh, pAl, pBh, pBl, 0, K, tid);
    load_stage(db, 1, pAh, pAl, pBh, pBl, 64, K, tid);

    for (int c = 0; c < NC; c++) {
        if (c + 1 < NC) cp_wait1(); else cp_wait0();
        __syncthreads();   // stage c resident; all warps done reading stage c-1

        if (c + 2 < NC)
            load_stage(db, (c + 2) % NSTAGE, pAh, pAl, pBh, pBl, (c + 2) * 64, K, tid);

        const uint32_t sb  = db + (c % NSTAGE) * STAGE_BYTES;
        const uint32_t tAh = sb;
        const uint32_t tAl = sb + TILE_BYTES;
        const uint32_t tBh = sb + 2 * TILE_BYTES;
        const uint32_t tBl = sb + 3 * TILE_BYTES;

        #pragma unroll
        for (int kk = 0; kk < 4; kk++) {
            const int c16 = (2 * kk + lc) * 16;
            uint32_t ah[4][4], al[4][4], bh[2][4], bl[2][4];
            #pragma unroll
            for (int mi = 0; mi < 4; mi++) {
                const uint32_t off = SW128((uint32_t)(wmr + mi * 16 + lr) * 128 + c16);
                ldsm_x4(ah[mi][0], ah[mi][1], ah[mi][2], ah[mi][3], tAh + off);
                ldsm_x4(al[mi][0], al[mi][1], al[mi][2], al[mi][3], tAl + off);
            }
            #pragma unroll
            for (int nb = 0; nb < 2; nb++) {
                const uint32_t off = SW128((uint32_t)(wnr + nb * 16 + lr) * 128 + c16);
                ldsm_x4(bh[nb][0], bh[nb][1], bh[nb][2], bh[nb][3], tBh + off);
                ldsm_x4(bl[nb][0], bl[nb][1], bl[nb][2], bl[nb][3], tBl + off);
            }
            // ldmatrix.x4 matrix order (our addressing):
            //   reg0 = n0-7|k0-7, reg1 = n8-15|k0-7, reg2 = n0-7|k8-15, reg3 = n8-15|k8-15
            // mma B fragment wants {k-lo, k-hi} of ONE n-block:
            //   n-block even -> (reg0, reg2); n-block odd -> (reg1, reg3)
            #pragma unroll
            for (int mi = 0; mi < 4; mi++)
                #pragma unroll
                for (int ni = 0; ni < 4; ni++) {
                    const int nb = ni >> 1, sel = ni & 1;
                    float* d = acc[mi][ni];
                    mma16816(d[0], d[1], d[2], d[3],
                             ah[mi][0], ah[mi][1], ah[mi][2], ah[mi][3],
                             bh[nb][sel], bh[nb][sel + 2]);
                    mma16816(d[0], d[1], d[2], d[3],
                             ah[mi][0], ah[mi][1], ah[mi][2], ah[mi][3],
                             bl[nb][sel], bl[nb][sel + 2]);
                    mma16816(d[0], d[1], d[2], d[3],
                             al[mi][0], al[mi][1], al[mi][2], al[mi][3],
                             bh[nb][sel], bh[nb][sel + 2]);
                }
        }
    }

    // epilogue: C fragment: d0,d1 -> (row g, col 2*tg), d2,d3 -> (row g+8, col 2*tg)
    const int g  = lane >> 2;
    const int tg = lane & 3;
    float* Cb = C + (size_t)b * M * N;
    #pragma unroll
    for (int mi = 0; mi < 4; mi++) {
        const int r0 = mr0 + wmr + mi * 16 + g;
        #pragma unroll
        for (int ni = 0; ni < 4; ni++) {
            const int col = nc0 + wnr + ni * 8 + 2 * tg;
            float2 v0 = make_float2(acc[mi][ni][0], acc[mi][ni][1]);
            float2 v1 = make_float2(acc[mi][ni][2], acc[mi][ni][3]);
            *(float2*)&Cb[(size_t)r0 * N + col]       = v0;
            *(float2*)&Cb[(size_t)(r0 + 8) * N + col] = v1;
        }
    }
}

// ---------------- split fp32 -> (hi, lo) bf16 for enc and dec ---------------
__device__ __forceinline__ void split1(float x, __nv_bfloat16& h, __nv_bfloat16& l) {
    h = __float2bfloat16(x);
    l = __float2bfloat16(x - __bfloat162float(h));
}

__global__ __launch_bounds__(256)
void split_inputs(const float* __restrict__ enc, const float* __restrict__ dec)
{
    const size_t nEnc4 = (size_t)BB * EE * DDIM / 4;
    size_t i = (size_t)blockIdx.x * blockDim.x + threadIdx.x;   // 8388608 total
    const float* src; __nv_bfloat16 *H, *L; size_t j;
    if (i < nEnc4) { src = enc; H = g_encH; L = g_encL; j = i; }
    else           { src = dec; H = g_decH; L = g_decL; j = i - nEnc4; }
    float4 v = ((const float4*)src)[j];
    __nv_bfloat16 h0, h1, h2, h3, l0, l1, l2, l3;
    split1(v.x, h0, l0); split1(v.y, h1, l1); split1(v.z, h2, l2); split1(v.w, h3, l3);
    *(__nv_bfloat162*)&H[j * 4]     = make_bfloat162(h0, h1);
    *(__nv_bfloat162*)&H[j * 4 + 2] = make_bfloat162(h2, h3);
    *(__nv_bfloat162*)&L[j * 4]     = make_bfloat162(l0, l1);
    *(__nv_bfloat162*)&L[j * 4 + 2] = make_bfloat162(l2, l3);
}

// ---------------- transpose + split: enc[b][e][d] -> encT[b][d][e] ----------
__global__ __launch_bounds__(256)
void transpose_split_enc(const float* __restrict__ enc)
{
    __shared__ float ts[32][33];
    const int b = blockIdx.z;
    const int d0 = blockIdx.x * 32;
    const int e0 = blockIdx.y * 32;
    const int tx = threadIdx.x, ty = threadIdx.y;   // (32, 8)
    const float* src = enc + (size_t)b * EE * DDIM;
    #pragma unroll
    for (int j = 0; j < 4; j++)
        ts[ty + 8 * j][tx] = src[(size_t)(e0 + ty + 8 * j) * DDIM + d0 + tx];
    __syncthreads();
    __nv_bfloat16* oh = g_encTH + (size_t)b * DDIM * EE;
    __nv_bfloat16* ol = g_encTL + (size_t)b * DDIM * EE;
    #pragma unroll
    for (int j = 0; j < 4; j++) {
        float v = ts[tx][ty + 8 * j];
        __nv_bfloat16 h, l; split1(v, h, l);
        size_t o = (size_t)(d0 + ty + 8 * j) * EE + e0 + tx;
        oh[o] = h; ol[o] = l;
    }
}

// ---------------- column softmax stats over t (partial + combine) -----------
__global__ __launch_bounds__(128)
void colstats_part()
{
    const int e = blockIdx.x * 128 + threadIdx.x;
    const int seg = blockIdx.y, b = blockIdx.z;
    const int T0 = TT / NSEG;
    const float* S = g_scores + (size_t)b * TT * EE + (size_t)seg * T0 * EE + e;
    float m = -1e30f, s = 0.f;
    for (int t = 0; t < T0; t += 4) {
        float x0 = S[(size_t)t * EE];
        float x1 = S[(size_t)(t + 1) * EE];
        float x2 = S[(size_t)(t + 2) * EE];
        float x3 = S[(size_t)(t + 3) * EE];
        float mm = fmaxf(fmaxf(x0, x1), fmaxf(x2, x3));
        float nm = fmaxf(m, mm);
        s = s * __expf(m - nm) + __expf(x0 - nm) + __expf(x1 - nm)
                               + __expf(x2 - nm) + __expf(x3 - nm);
        m = nm;
    }
    const int idx = (b * NSEG + seg) * EE + e;
    g_mpart[idx] = m; g_spart[idx] = s;
}

__global__ __launch_bounds__(256)
void colstats_comb()
{
    const int i = blockIdx.x * 256 + threadIdx.x;   // over BB*EE
    const int b = i / EE, e = i % EE;
    float M = -1e30f;
    #pragma unroll
    for (int s = 0; s < NSEG; s++)
        M = fmaxf(M, g_mpart[(b * NSEG + s) * EE + e]);
    float S = 0.f;
    #pragma unroll
    for (int s = 0; s < NSEG; s++) {
        int idx = (b * NSEG + s) * EE + e;
        S += g_spart[idx] * __expf(g_mpart[idx] - M);
    }
    g_colM[i] = M;
    g_colIS[i] = 1.0f / S;
}

// ---------------- normalize + split: scores -> PtH/PtL ----------------------
__global__ __launch_bounds__(256)
void softmax_split()
{
    size_t i = ((size_t)blockIdx.x * blockDim.x + threadIdx.x) * 4;  // [b][t][e]
    const int e = (int)(i % EE);
    const int b = (int)(i / ((size_t)TT * EE));
    float4 v = *(const float4*)&g_scores[i];
    float4 m4 = *(const float4*)&g_colM[b * EE + e];
    float4 s4 = *(const float4*)&g_colIS[b * EE + e];
    float p0 = __expf(v.x - m4.x) * s4.x;
    float p1 = __expf(v.y - m4.y) * s4.y;
    float p2 = __expf(v.z - m4.z) * s4.z;
    float p3 = __expf(v.w - m4.w) * s4.w;
    __nv_bfloat16 h0, h1, h2, h3, l0, l1, l2, l3;
    split1(p0, h0, l0); split1(p1, h1, l1); split1(p2, h2, l2); split1(p3, h3, l3);
    *(__nv_bfloat162*)&g_ptH[i]     = make_bfloat162(h0, h1);
    *(__nv_bfloat162*)&g_ptH[i + 2] = make_bfloat162(h2, h3);
    *(__nv_bfloat162*)&g_ptL[i]     = make_bfloat162(l0, l1);
    *(__nv_bfloat162*)&g_ptL[i + 2] = make_bfloat162(l2, l3);
}

// ---------------------------------------------------------------------------
extern "C" void kernel_launch(void* const* d_in, const int* in_sizes, int n_in,
                              void* d_out, int out_size)
{
    const float* enc = (const float*)d_in[0];
    const float* dec = (const float*)d_in[1];
    float* out = (float*)d_out;

    cudaFuncSetAttribute(gemm_bf16x3, cudaFuncAttributeMaxDynamicSharedMemorySize,
                         GEMM_SMEM);

    split_inputs<<<32768, 256>>>(enc, dec);
    {
        dim3 g(DDIM / 32, EE / 32, BB);
        transpose_split_enc<<<g, dim3(32, 8)>>>(enc);
    }
    {
        dim3 g(EE / 128, TT / 128, BB);
        gemm_bf16x3<<<g, 256, GEMM_SMEM>>>(out, 0);
    }
    {
        dim3 g(EE / 128, NSEG, BB);
        colstats_part<<<g, 128>>>();
    }
    colstats_comb<<<BB * EE / 256, 256>>>();
    softmax_split<<<32768, 256>>>();
    {
        dim3 g(DDIM / 128, TT / 128, BB);
        gemm_bf16x3<<<g, 256, GEMM_SMEM>>>(out, 1);
    }
}

// round 13
// speedup vs baseline: 2.4693x; 1.0290x over previous
#include <cuda_runtime.h>
#include <cuda_bf16.h>
#include <cstdint>
#include <cstddef>

#define BB 8
#define TT 2048      // S_dec
#define EE 2048      // S_enc
#define DDIM 1024    // D

// ---------------- scratch (static device arrays; no allocation) ------------
__device__ float g_scores[(size_t)BB * TT * EE];                 // [b][t][e] fp32
__device__ __nv_bfloat16 g_encH[(size_t)BB * EE * DDIM];
__device__ __nv_bfloat16 g_encL[(size_t)BB * EE * DDIM];
__device__ __nv_bfloat16 g_decH[(size_t)BB * TT * DDIM];
__device__ __nv_bfloat16 g_decL[(size_t)BB * TT * DDIM];
__device__ __nv_bfloat16 g_encTH[(size_t)BB * DDIM * EE];        // [b][d][e]
__device__ __nv_bfloat16 g_encTL[(size_t)BB * DDIM * EE];
__device__ __nv_bfloat16 g_ptH[(size_t)BB * TT * EE];            // P^T [b][t][e]
__device__ __nv_bfloat16 g_ptL[(size_t)BB * TT * EE];
#define NSEG 32                                                   // TT/128 * 2 warp-rows
__device__ float g_mpart[NSEG * BB * EE];
__device__ float g_spart[NSEG * BB * EE];
__device__ float g_colM[BB * EE];
__device__ float g_colIS[BB * EE];

// ---------------- helpers ---------------------------------------------------
__device__ __forceinline__ uint32_t smem_u32(const void* p) {
    uint32_t a;
    asm("{ .reg .u64 t; cvta.to.shared.u64 t, %1; cvt.u32.u64 %0, t; }"
        : "=r"(a) : "l"(p));
    return a;
}
__device__ __forceinline__ void cp_async16(uint32_t s, const void* g) {
    asm volatile("cp.async.cg.shared.global [%0], [%1], 16;" :: "r"(s), "l"(g) : "memory");
}
__device__ __forceinline__ void cp_commit() {
    asm volatile("cp.async.commit_group;" ::: "memory");
}
__device__ __forceinline__ void cp_wait1() { asm volatile("cp.async.wait_group 1;" ::: "memory"); }
__device__ __forceinline__ void cp_wait0() { asm volatile("cp.async.wait_group 0;" ::: "memory"); }

__device__ __forceinline__ void ldsm_x4(uint32_t& r0, uint32_t& r1, uint32_t& r2, uint32_t& r3,
                                        uint32_t addr) {
    asm volatile("ldmatrix.sync.aligned.m8n8.x4.shared.b16 {%0,%1,%2,%3}, [%4];"
        : "=r"(r0), "=r"(r1), "=r"(r2), "=r"(r3) : "r"(addr));
}
__device__ __forceinline__ void mma16816(float& d0, float& d1, float& d2, float& d3,
                                         uint32_t a0, uint32_t a1, uint32_t a2, uint32_t a3,
                                         uint32_t b0, uint32_t b1) {
    asm volatile("mma.sync.aligned.m16n8k16.row.col.f32.bf16.bf16.f32 "
                 "{%0,%1,%2,%3}, {%4,%5,%6,%7}, {%8,%9}, {%0,%1,%2,%3};"
                 : "+f"(d0), "+f"(d1), "+f"(d2), "+f"(d3)
                 : "r"(a0), "r"(a1), "r"(a2), "r"(a3), "r"(b0), "r"(b1));
}

#define SW128(o) ((o) ^ (((o) >> 3) & 0x70))
#define TILE_BYTES 16384                   // 128 rows x 128B (64 bf16)
#define STAGE_BYTES (4 * TILE_BYTES)       // Ah, Al, Bh, Bl
#define NSTAGE 3
#define GEMM_SMEM (1024 + NSTAGE * STAGE_BYTES)

// load one 64-K-wide stage: 4 operand tiles of 128 rows x 64 bf16
__device__ __forceinline__ void load_stage(uint32_t db, int stage,
    const __nv_bfloat16* pAh, const __nv_bfloat16* pAl,
    const __nv_bfloat16* pBh, const __nv_bfloat16* pBl,
    int k0, int K, int tid)
{
    const __nv_bfloat16* srcs[4] = { pAh + k0, pAl + k0, pBh + k0, pBl + k0 };
    uint32_t sbase = db + stage * STAGE_BYTES;
    #pragma unroll
    for (int tt = 0; tt < 4; tt++) {
        const __nv_bfloat16* s = srcs[tt];
        uint32_t tb = sbase + tt * TILE_BYTES;
        #pragma unroll
        for (int ii = 0; ii < 4; ii++) {
            int i = tid + ii * 256;
            int r = i >> 3, c = i & 7;
            cp_async16(tb + SW128(r * 128 + c * 16), s + (size_t)r * K + c * 8);
        }
    }
    cp_commit();
}

// ---------------- GEMM: C[M,N] = 3-term-split A[M,K] * B[N,K]^T -------------
// which==0 additionally emits per-column (over this CTA's 128 rows, split per
// warp-row half) softmax partials: max and sum-exp -> g_mpart/g_spart.
__global__ __launch_bounds__(256, 1)
void gemm_bf16x3(float* __restrict__ outPtr, int which)
{
    const __nv_bfloat16 *aH, *aL, *bH, *bL;
    float* C;
    int M, N, K;
    if (which == 0) {  // scores^T: C[t][e] = sum_d dec[t,d] * enc[e,d]
        aH = g_decH; aL = g_decL; bH = g_encH; bL = g_encL;
        C = g_scores; M = TT; N = EE; K = DDIM;
    } else {           // out[t][d] = sum_e Pt[t,e] * encT[d,e]
        aH = g_ptH; aL = g_ptL; bH = g_encTH; bL = g_encTL;
        C = outPtr; M = TT; N = DDIM; K = EE;
    }

    extern __shared__ char dsm[];
    const uint32_t db = (smem_u32(dsm) + 1023u) & ~1023u;

    const int tid  = threadIdx.x;
    const int wid  = tid >> 5;
    const int lane = tid & 31;
    const int b    = blockIdx.z;
    const int nc0  = blockIdx.x * 128;
    const int mr0  = blockIdx.y * 128;

    const int wm = wid & 1;          // 2 warps in M
    const int wn = wid >> 1;         // 4 warps in N
    const int wmr = wm * 64;         // warp row offset in tile
    const int wnr = wn * 32;         // warp col offset in tile

    // ldmatrix lane addressing: sub = lane>>3
    const int sub = lane >> 3;
    const int lr  = ((sub & 1) << 3) + (lane & 7);  // row within 16-row block
    const int lc  = sub >> 1;                        // kchunk (16B) within k16

    const __nv_bfloat16* pAh = aH + (size_t)b * M * K + (size_t)mr0 * K;
    const __nv_bfloat16* pAl = aL + (size_t)b * M * K + (size_t)mr0 * K;
    const __nv_bfloat16* pBh = bH + (size_t)b * N * K + (size_t)nc0 * K;
    const __nv_bfloat16* pBl = bL + (size_t)b * N * K + (size_t)nc0 * K;

    float acc[4][4][4];
    #pragma unroll
    for (int i = 0; i < 4; i++)
        #pragma unroll
        for (int j = 0; j < 4; j++) {
            acc[i][j][0] = 0.f; acc[i][j][1] = 0.f;
            acc[i][j][2] = 0.f; acc[i][j][3] = 0.f;
        }

    const int NC = K / 64;
    load_stage(db, 0, pAh, pAl, pBh, pBl, 0, K, tid);
    load_stage(db, 1, pAh, pAl, pBh, pBl, 64, K, tid);

    for (int c = 0; c < NC; c++) {
        if (c + 1 < NC) cp_wait1(); else cp_wait0();
        __syncthreads();   // stage c resident; all warps done reading stage c-1

        if (c + 2 < NC)
            load_stage(db, (c + 2) % NSTAGE, pAh, pAl, pBh, pBl, (c + 2) * 64, K, tid);

        const uint32_t sb  = db + (c % NSTAGE) * STAGE_BYTES;
        const uint32_t tAh = sb;
        const uint32_t tAl = sb + TILE_BYTES;
        const uint32_t tBh = sb + 2 * TILE_BYTES;
        const uint32_t tBl = sb + 3 * TILE_BYTES;

        #pragma unroll
        for (int kk = 0; kk < 4; kk++) {
            const int c16 = (2 * kk + lc) * 16;
            uint32_t ah[4][4], al[4][4], bh[2][4], bl[2][4];
            #pragma unroll
            for (int mi = 0; mi < 4; mi++) {
                const uint32_t off = SW128((uint32_t)(wmr + mi * 16 + lr) * 128 + c16);
                ldsm_x4(ah[mi][0], ah[mi][1], ah[mi][2], ah[mi][3], tAh + off);
                ldsm_x4(al[mi][0], al[mi][1], al[mi][2], al[mi][3], tAl + off);
            }
            #pragma unroll
            for (int nb = 0; nb < 2; nb++) {
                const uint32_t off = SW128((uint32_t)(wnr + nb * 16 + lr) * 128 + c16);
                ldsm_x4(bh[nb][0], bh[nb][1], bh[nb][2], bh[nb][3], tBh + off);
                ldsm_x4(bl[nb][0], bl[nb][1], bl[nb][2], bl[nb][3], tBl + off);
            }
            // ldmatrix.x4 matrix order (our addressing):
            //   reg0 = n0-7|k0-7, reg1 = n8-15|k0-7, reg2 = n0-7|k8-15, reg3 = n8-15|k8-15
            // mma B fragment wants {k-lo, k-hi} of ONE n-block:
            //   n-block even -> (reg0, reg2); n-block odd -> (reg1, reg3)
            #pragma unroll
            for (int mi = 0; mi < 4; mi++)
                #pragma unroll
                for (int ni = 0; ni < 4; ni++) {
                    const int nb = ni >> 1, sel = ni & 1;
                    float* d = acc[mi][ni];
                    mma16816(d[0], d[1], d[2], d[3],
                             ah[mi][0], ah[mi][1], ah[mi][2], ah[mi][3],
                             bh[nb][sel], bh[nb][sel + 2]);
                    mma16816(d[0], d[1], d[2], d[3],
                             ah[mi][0], ah[mi][1], ah[mi][2], ah[mi][3],
                             bl[nb][sel], bl[nb][sel + 2]);
                    mma16816(d[0], d[1], d[2], d[3],
                             al[mi][0], al[mi][1], al[mi][2], al[mi][3],
                             bh[nb][sel], bh[nb][sel + 2]);
                }
        }
    }

    // epilogue: C fragment: d0,d1 -> (row g, col 2*tg), d2,d3 -> (row g+8, col 2*tg)
    const int g  = lane >> 2;
    const int tg = lane & 3;
    float* Cb = C + (size_t)b * M * N;
    #pragma unroll
    for (int mi = 0; mi < 4; mi++) {
        const int r0 = mr0 + wmr + mi * 16 + g;
        #pragma unroll
        for (int ni = 0; ni < 4; ni++) {
            const int col = nc0 + wnr + ni * 8 + 2 * tg;
            float2 v0 = make_float2(acc[mi][ni][0], acc[mi][ni][1]);
            float2 v1 = make_float2(acc[mi][ni][2], acc[mi][ni][3]);
            *(float2*)&Cb[(size_t)r0 * N + col]       = v0;
            *(float2*)&Cb[(size_t)(r0 + 8) * N + col] = v1;
        }
    }

    // fused column softmax partials over this warp's 64 rows (scores GEMM only)
    if (which == 0) {
        const int seg = blockIdx.y * 2 + wm;               // 0..31
        float* mp = g_mpart + ((size_t)b * NSEG + seg) * EE;
        float* sp = g_spart + ((size_t)b * NSEG + seg) * EE;
        #pragma unroll
        for (int ni = 0; ni < 4; ni++) {
            float m0 = -1e30f, m1 = -1e30f;
            #pragma unroll
            for (int mi = 0; mi < 4; mi++) {
                m0 = fmaxf(m0, fmaxf(acc[mi][ni][0], acc[mi][ni][2]));
                m1 = fmaxf(m1, fmaxf(acc[mi][ni][1], acc[mi][ni][3]));
            }
            #pragma unroll
            for (int o = 4; o < 32; o <<= 1) {
                m0 = fmaxf(m0, __shfl_xor_sync(0xffffffffu, m0, o));
                m1 = fmaxf(m1, __shfl_xor_sync(0xffffffffu, m1, o));
            }
            float s0 = 0.f, s1 = 0.f;
            #pragma unroll
            for (int mi = 0; mi < 4; mi++) {
                s0 += __expf(acc[mi][ni][0] - m0) + __expf(acc[mi][ni][2] - m0);
                s1 += __expf(acc[mi][ni][1] - m1) + __expf(acc[mi][ni][3] - m1);
            }
            #pragma unroll
            for (int o = 4; o < 32; o <<= 1) {
                s0 += __shfl_xor_sync(0xffffffffu, s0, o);
                s1 += __shfl_xor_sync(0xffffffffu, s1, o);
            }
            if (lane < 4) {   // g==0 lanes; tg == lane
                const int e = nc0 + wnr + ni * 8 + 2 * lane;
                mp[e] = m0; mp[e + 1] = m1;
                sp[e] = s0; sp[e + 1] = s1;
            }
        }
    }
}

// ---------------- split fp32 -> (hi, lo) bf16 -------------------------------
__device__ __forceinline__ void split1(float x, __nv_bfloat16& h, __nv_bfloat16& l) {
    h = __float2bfloat16(x);
    l = __float2bfloat16(x - __bfloat162float(h));
}

// dec: row-major split only
__global__ __launch_bounds__(256)
void split_dec(const float* __restrict__ dec)
{
    size_t j = (size_t)blockIdx.x * blockDim.x + threadIdx.x;   // over 4.19M float4
    float4 v = ((const float4*)dec)[j];
    __nv_bfloat16 h0, h1, h2, h3, l0, l1, l2, l3;
    split1(v.x, h0, l0); split1(v.y, h1, l1); split1(v.z, h2, l2); split1(v.w, h3, l3);
    *(__nv_bfloat162*)&g_decH[j * 4]     = make_bfloat162(h0, h1);
    *(__nv_bfloat162*)&g_decH[j * 4 + 2] = make_bfloat162(h2, h3);
    *(__nv_bfloat162*)&g_decL[j * 4]     = make_bfloat162(l0, l1);
    *(__nv_bfloat162*)&g_decL[j * 4 + 2] = make_bfloat162(l2, l3);
}

// enc: single read -> row-major split (encH/encL) + transposed split (encTH/encTL)
__global__ __launch_bounds__(256)
void split_enc_fused(const float* __restrict__ enc)
{
    __shared__ float ts[32][33];
    const int b = blockIdx.z;
    const int d0 = blockIdx.x * 32;
    const int e0 = blockIdx.y * 32;
    const int tx = threadIdx.x, ty = threadIdx.y;   // (32, 8)
    const float* src = enc + (size_t)b * EE * DDIM;
    __nv_bfloat16* rh = g_encH + (size_t)b * EE * DDIM;
    __nv_bfloat16* rl = g_encL + (size_t)b * EE * DDIM;
    #pragma unroll
    for (int j = 0; j < 4; j++) {
        const size_t o = (size_t)(e0 + ty + 8 * j) * DDIM + d0 + tx;
        float v = src[o];
        ts[ty + 8 * j][tx] = v;
        __nv_bfloat16 h, l; split1(v, h, l);
        rh[o] = h; rl[o] = l;
    }
    __syncthreads();
    __nv_bfloat16* oh = g_encTH + (size_t)b * DDIM * EE;
    __nv_bfloat16* ol = g_encTL + (size_t)b * DDIM * EE;
    #pragma unroll
    for (int j = 0; j < 4; j++) {
        float v = ts[tx][ty + 8 * j];
        __nv_bfloat16 h, l; split1(v, h, l);
        size_t o = (size_t)(d0 + ty + 8 * j) * EE + e0 + tx;
        oh[o] = h; ol[o] = l;
    }
}

// ---------------- combine 32 segments -> column max & inv-sum ---------------
__global__ __launch_bounds__(256)
void colstats_comb()
{
    const int i = blockIdx.x * 256 + threadIdx.x;   // over BB*EE
    const int b = i / EE, e = i % EE;
    float M = -1e30f;
    #pragma unroll
    for (int s = 0; s < NSEG; s++)
        M = fmaxf(M, g_mpart[((size_t)b * NSEG + s) * EE + e]);
    float S = 0.f;
    #pragma unroll
    for (int s = 0; s < NSEG; s++) {
        size_t idx = ((size_t)b * NSEG + s) * EE + e;
        S += g_spart[idx] * __expf(g_mpart[idx] - M);
    }
    g_colM[i] = M;
    g_colIS[i] = 1.0f / S;
}

// ---------------- normalize + split: scores -> PtH/PtL ----------------------
__global__ __launch_bounds__(256)
void softmax_split()
{
    size_t i = ((size_t)blockIdx.x * blockDim.x + threadIdx.x) * 4;  // [b][t][e]
    const int e = (int)(i % EE);
    const int b = (int)(i / ((size_t)TT * EE));
    float4 v = *(const float4*)&g_scores[i];
    float4 m4 = *(const float4*)&g_colM[b * EE + e];
    float4 s4 = *(const float4*)&g_colIS[b * EE + e];
    float p0 = __expf(v.x - m4.x) * s4.x;
    float p1 = __expf(v.y - m4.y) * s4.y;
    float p2 = __expf(v.z - m4.z) * s4.z;
    float p3 = __expf(v.w - m4.w) * s4.w;
    __nv_bfloat16 h0, h1, h2, h3, l0, l1, l2, l3;
    split1(p0, h0, l0); split1(p1, h1, l1); split1(p2, h2, l2); split1(p3, h3, l3);
    *(__nv_bfloat162*)&g_ptH[i]     = make_bfloat162(h0, h1);
    *(__nv_bfloat162*)&g_ptH[i + 2] = make_bfloat162(h2, h3);
    *(__nv_bfloat162*)&g_ptL[i]     = make_bfloat162(l0, l1);
    *(__nv_bfloat162*)&g_ptL[i + 2] = make_bfloat162(l2, l3);
}

// ---------------------------------------------------------------------------
extern "C" void kernel_launch(void* const* d_in, const int* in_sizes, int n_in,
                              void* d_out, int out_size)
{
    const float* enc = (const float*)d_in[0];
    const float* dec = (const float*)d_in[1];
    float* out = (float*)d_out;

    cudaFuncSetAttribute(gemm_bf16x3, cudaFuncAttributeMaxDynamicSharedMemorySize,
                         GEMM_SMEM);

    {
        dim3 g(DDIM / 32, EE / 32, BB);
        split_enc_fused<<<g, dim3(32, 8)>>>(enc);
    }
    split_dec<<<16384, 256>>>(dec);
    {
        dim3 g(EE / 128, TT / 128, BB);
        gemm_bf16x3<<<g, 256, GEMM_SMEM>>>(out, 0);
    }
    colstats_comb<<<BB * EE / 256, 256>>>();
    softmax_split<<<32768, 256>>>();
    {
        dim3 g(DDIM / 128, TT / 128, BB);
        gemm_bf16x3<<<g, 256, GEMM_SMEM>>>(out, 1);
    }
}

// round 14
// speedup vs baseline: 2.4799x; 1.0043x over previous
#include <cuda_runtime.h>
#include <cuda_bf16.h>
#include <cstdint>
#include <cstddef>

#define BB 8
#define TT 2048      // S_dec
#define EE 2048      // S_enc
#define DDIM 1024    // D

// ---------------- scratch (static device arrays; no allocation) ------------
__device__ float g_scores[(size_t)BB * TT * EE];                 // [b][t][e] fp32
__device__ __nv_bfloat16 g_encH[(size_t)BB * EE * DDIM];
__device__ __nv_bfloat16 g_encL[(size_t)BB * EE * DDIM];
__device__ __nv_bfloat16 g_decH[(size_t)BB * TT * DDIM];
__device__ __nv_bfloat16 g_decL[(size_t)BB * TT * DDIM];
__device__ __nv_bfloat16 g_encTH[(size_t)BB * DDIM * EE];        // [b][d][e]
__device__ __nv_bfloat16 g_encTL[(size_t)BB * DDIM * EE];
__device__ __nv_bfloat16 g_ptH[(size_t)BB * TT * EE];            // P^T [b][t][e]
__device__ __nv_bfloat16 g_ptL[(size_t)BB * TT * EE];
#define NSEG 32                                                   // TT/128 * 2 warp-rows
__device__ float g_mpart[NSEG * BB * EE];
__device__ float g_spart[NSEG * BB * EE];
__device__ float g_colM[BB * EE];
__device__ float g_colIS[BB * EE];

// ---------------- helpers ---------------------------------------------------
__device__ __forceinline__ uint32_t smem_u32(const void* p) {
    uint32_t a;
    asm("{ .reg .u64 t; cvta.to.shared.u64 t, %1; cvt.u32.u64 %0, t; }"
        : "=r"(a) : "l"(p));
    return a;
}
__device__ __forceinline__ void cp_async16(uint32_t s, const void* g) {
    asm volatile("cp.async.cg.shared.global [%0], [%1], 16;" :: "r"(s), "l"(g) : "memory");
}
__device__ __forceinline__ void cp_commit() {
    asm volatile("cp.async.commit_group;" ::: "memory");
}
__device__ __forceinline__ void cp_wait1() { asm volatile("cp.async.wait_group 1;" ::: "memory"); }
__device__ __forceinline__ void cp_wait0() { asm volatile("cp.async.wait_group 0;" ::: "memory"); }

__device__ __forceinline__ void ldsm_x4(uint32_t& r0, uint32_t& r1, uint32_t& r2, uint32_t& r3,
                                        uint32_t addr) {
    asm volatile("ldmatrix.sync.aligned.m8n8.x4.shared.b16 {%0,%1,%2,%3}, [%4];"
        : "=r"(r0), "=r"(r1), "=r"(r2), "=r"(r3) : "r"(addr));
}
__device__ __forceinline__ void mma16816(float& d0, float& d1, float& d2, float& d3,
                                         uint32_t a0, uint32_t a1, uint32_t a2, uint32_t a3,
                                         uint32_t b0, uint32_t b1) {
    asm volatile("mma.sync.aligned.m16n8k16.row.col.f32.bf16.bf16.f32 "
                 "{%0,%1,%2,%3}, {%4,%5,%6,%7}, {%8,%9}, {%0,%1,%2,%3};"
                 : "+f"(d0), "+f"(d1), "+f"(d2), "+f"(d3)
                 : "r"(a0), "r"(a1), "r"(a2), "r"(a3), "r"(b0), "r"(b1));
}

#define SW128(o) ((o) ^ (((o) >> 3) & 0x70))
#define TILE_BYTES 16384                   // 128 rows x 128B (64 bf16)
#define STAGE_BYTES (4 * TILE_BYTES)       // Ah, Al, Bh, Bl
#define NSTAGE 3
#define GEMM_SMEM (1024 + NSTAGE * STAGE_BYTES)

// register fragment set for one k16 step
struct Frag {
    uint32_t ah[4][4];
    uint32_t al[4][4];
    uint32_t bh[2][4];
    uint32_t bl[2][4];
};

// load one 64-K-wide stage: 4 operand tiles of 128 rows x 64 bf16
__device__ __forceinline__ void load_stage(uint32_t db, int stage,
    const __nv_bfloat16* pAh, const __nv_bfloat16* pAl,
    const __nv_bfloat16* pBh, const __nv_bfloat16* pBl,
    int k0, int K, int tid)
{
    const __nv_bfloat16* srcs[4] = { pAh + k0, pAl + k0, pBh + k0, pBl + k0 };
    uint32_t sbase = db + stage * STAGE_BYTES;
    #pragma unroll
    for (int tt = 0; tt < 4; tt++) {
        const __nv_bfloat16* s = srcs[tt];
        uint32_t tb = sbase + tt * TILE_BYTES;
        #pragma unroll
        for (int ii = 0; ii < 4; ii++) {
            int i = tid + ii * 256;
            int r = i >> 3, c = i & 7;
            cp_async16(tb + SW128(r * 128 + c * 16), s + (size_t)r * K + c * 8);
        }
    }
    cp_commit();
}

// load all fragments for k16 step kk from the resident stage
__device__ __forceinline__ void load_frags(Frag& f,
    uint32_t tAh, uint32_t tAl, uint32_t tBh, uint32_t tBl,
    int kk, int lc, int lr, int wmr, int wnr)
{
    const int c16 = (2 * kk + lc) * 16;
    #pragma unroll
    for (int mi = 0; mi < 4; mi++) {
        const uint32_t off = SW128((uint32_t)(wmr + mi * 16 + lr) * 128 + c16);
        ldsm_x4(f.ah[mi][0], f.ah[mi][1], f.ah[mi][2], f.ah[mi][3], tAh + off);
        ldsm_x4(f.al[mi][0], f.al[mi][1], f.al[mi][2], f.al[mi][3], tAl + off);
    }
    #pragma unroll
    for (int nb = 0; nb < 2; nb++) {
        const uint32_t off = SW128((uint32_t)(wnr + nb * 16 + lr) * 128 + c16);
        ldsm_x4(f.bh[nb][0], f.bh[nb][1], f.bh[nb][2], f.bh[nb][3], tBh + off);
        ldsm_x4(f.bl[nb][0], f.bl[nb][1], f.bl[nb][2], f.bl[nb][3], tBl + off);
    }
}

// issue the 48 MMAs (3 split terms x 16 micro-tiles) for one fragment set
__device__ __forceinline__ void mma_frags(float acc[4][4][4], const Frag& f)
{
    // ldmatrix.x4 matrix order (our addressing):
    //   reg0 = n0-7|k0-7, reg1 = n8-15|k0-7, reg2 = n0-7|k8-15, reg3 = n8-15|k8-15
    // mma B fragment wants {k-lo, k-hi} of ONE n-block:
    //   n-block even -> (reg0, reg2); n-block odd -> (reg1, reg3)
    #pragma unroll
    for (int mi = 0; mi < 4; mi++)
        #pragma unroll
        for (int ni = 0; ni < 4; ni++) {
            const int nb = ni >> 1, sel = ni & 1;
            float* d = acc[mi][ni];
            mma16816(d[0], d[1], d[2], d[3],
                     f.ah[mi][0], f.ah[mi][1], f.ah[mi][2], f.ah[mi][3],
                     f.bh[nb][sel], f.bh[nb][sel + 2]);
            mma16816(d[0], d[1], d[2], d[3],
                     f.ah[mi][0], f.ah[mi][1], f.ah[mi][2], f.ah[mi][3],
                     f.bl[nb][sel], f.bl[nb][sel + 2]);
            mma16816(d[0], d[1], d[2], d[3],
                     f.al[mi][0], f.al[mi][1], f.al[mi][2], f.al[mi][3],
                     f.bh[nb][sel], f.bh[nb][sel + 2]);
        }
}

// ---------------- GEMM: C[M,N] = 3-term-split A[M,K] * B[N,K]^T -------------
// which==0 additionally emits per-column (over this CTA's 128 rows, split per
// warp-row half) softmax partials: max and sum-exp -> g_mpart/g_spart.
__global__ __launch_bounds__(256, 1)
void gemm_bf16x3(float* __restrict__ outPtr, int which)
{
    const __nv_bfloat16 *aH, *aL, *bH, *bL;
    float* C;
    int M, N, K;
    if (which == 0) {  // scores^T: C[t][e] = sum_d dec[t,d] * enc[e,d]
        aH = g_decH; aL = g_decL; bH = g_encH; bL = g_encL;
        C = g_scores; M = TT; N = EE; K = DDIM;
    } else {           // out[t][d] = sum_e Pt[t,e] * encT[d,e]
        aH = g_ptH; aL = g_ptL; bH = g_encTH; bL = g_encTL;
        C = outPtr; M = TT; N = DDIM; K = EE;
    }

    extern __shared__ char dsm[];
    const uint32_t db = (smem_u32(dsm) + 1023u) & ~1023u;

    const int tid  = threadIdx.x;
    const int wid  = tid >> 5;
    const int lane = tid & 31;
    const int b    = blockIdx.z;
    const int nc0  = blockIdx.x * 128;
    const int mr0  = blockIdx.y * 128;

    const int wm = wid & 1;          // 2 warps in M
    const int wn = wid >> 1;         // 4 warps in N
    const int wmr = wm * 64;         // warp row offset in tile
    const int wnr = wn * 32;         // warp col offset in tile

    // ldmatrix lane addressing: sub = lane>>3
    const int sub = lane >> 3;
    const int lr  = ((sub & 1) << 3) + (lane & 7);  // row within 16-row block
    const int lc  = sub >> 1;                        // kchunk (16B) within k16

    const __nv_bfloat16* pAh = aH + (size_t)b * M * K + (size_t)mr0 * K;
    const __nv_bfloat16* pAl = aL + (size_t)b * M * K + (size_t)mr0 * K;
    const __nv_bfloat16* pBh = bH + (size_t)b * N * K + (size_t)nc0 * K;
    const __nv_bfloat16* pBl = bL + (size_t)b * N * K + (size_t)nc0 * K;

    float acc[4][4][4];
    #pragma unroll
    for (int i = 0; i < 4; i++)
        #pragma unroll
        for (int j = 0; j < 4; j++) {
            acc[i][j][0] = 0.f; acc[i][j][1] = 0.f;
            acc[i][j][2] = 0.f; acc[i][j][3] = 0.f;
        }

    const int NC = K / 64;
    load_stage(db, 0, pAh, pAl, pBh, pBl, 0, K, tid);
    load_stage(db, 1, pAh, pAl, pBh, pBl, 64, K, tid);

    Frag fr[2];
    for (int c = 0; c < NC; c++) {
        if (c + 1 < NC) cp_wait1(); else cp_wait0();
        __syncthreads();   // stage c resident; all warps done reading stage c-1

        if (c + 2 < NC)
            load_stage(db, (c + 2) % NSTAGE, pAh, pAl, pBh, pBl, (c + 2) * 64, K, tid);

        const uint32_t sb  = db + (c % NSTAGE) * STAGE_BYTES;
        const uint32_t tAh = sb;
        const uint32_t tAl = sb + TILE_BYTES;
        const uint32_t tBh = sb + 2 * TILE_BYTES;
        const uint32_t tBl = sb + 3 * TILE_BYTES;

        // 2-deep register pipeline over the 4 k16 steps
        load_frags(fr[0], tAh, tAl, tBh, tBl, 0, lc, lr, wmr, wnr);
        #pragma unroll
        for (int kk = 0; kk < 4; kk++) {
            if (kk < 3)
                load_frags(fr[(kk + 1) & 1], tAh, tAl, tBh, tBl, kk + 1, lc, lr, wmr, wnr);
            mma_frags(acc, fr[kk & 1]);
        }
    }

    // epilogue: C fragment: d0,d1 -> (row g, col 2*tg), d2,d3 -> (row g+8, col 2*tg)
    const int g  = lane >> 2;
    const int tg = lane & 3;
    float* Cb = C + (size_t)b * M * N;
    #pragma unroll
    for (int mi = 0; mi < 4; mi++) {
        const int r0 = mr0 + wmr + mi * 16 + g;
        #pragma unroll
        for (int ni = 0; ni < 4; ni++) {
            const int col = nc0 + wnr + ni * 8 + 2 * tg;
            float2 v0 = make_float2(acc[mi][ni][0], acc[mi][ni][1]);
            float2 v1 = make_float2(acc[mi][ni][2], acc[mi][ni][3]);
            *(float2*)&Cb[(size_t)r0 * N + col]       = v0;
            *(float2*)&Cb[(size_t)(r0 + 8) * N + col] = v1;
        }
    }

    // fused column softmax partials over this warp's 64 rows (scores GEMM only)
    if (which == 0) {
        const int seg = blockIdx.y * 2 + wm;               // 0..31
        float* mp = g_mpart + ((size_t)b * NSEG + seg) * EE;
        float* sp = g_spart + ((size_t)b * NSEG + seg) * EE;
        #pragma unroll
        for (int ni = 0; ni < 4; ni++) {
            float m0 = -1e30f, m1 = -1e30f;
            #pragma unroll
            for (int mi = 0; mi < 4; mi++) {
                m0 = fmaxf(m0, fmaxf(acc[mi][ni][0], acc[mi][ni][2]));
                m1 = fmaxf(m1, fmaxf(acc[mi][ni][1], acc[mi][ni][3]));
            }
            #pragma unroll
            for (int o = 4; o < 32; o <<= 1) {
                m0 = fmaxf(m0, __shfl_xor_sync(0xffffffffu, m0, o));
                m1 = fmaxf(m1, __shfl_xor_sync(0xffffffffu, m1, o));
            }
            float s0 = 0.f, s1 = 0.f;
            #pragma unroll
            for (int mi = 0; mi < 4; mi++) {
                s0 += __expf(acc[mi][ni][0] - m0) + __expf(acc[mi][ni][2] - m0);
                s1 += __expf(acc[mi][ni][1] - m1) + __expf(acc[mi][ni][3] - m1);
            }
            #pragma unroll
            for (int o = 4; o < 32; o <<= 1) {
                s0 += __shfl_xor_sync(0xffffffffu, s0, o);
                s1 += __shfl_xor_sync(0xffffffffu, s1, o);
            }
            if (lane < 4) {   // g==0 lanes; tg == lane
                const int e = nc0 + wnr + ni * 8 + 2 * lane;
                mp[e] = m0; mp[e + 1] = m1;
                sp[e] = s0; sp[e + 1] = s1;
            }
        }
    }
}

// ---------------- split fp32 -> (hi, lo) bf16 -------------------------------
__device__ __forceinline__ void split1(float x, __nv_bfloat16& h, __nv_bfloat16& l) {
    h = __float2bfloat16(x);
    l = __float2bfloat16(x - __bfloat162float(h));
}

// dec: row-major split only
__global__ __launch_bounds__(256)
void split_dec(const float* __restrict__ dec)
{
    size_t j = (size_t)blockIdx.x * blockDim.x + threadIdx.x;   // over 4.19M float4
    float4 v = ((const float4*)dec)[j];
    __nv_bfloat16 h0, h1, h2, h3, l0, l1, l2, l3;
    split1(v.x, h0, l0); split1(v.y, h1, l1); split1(v.z, h2, l2); split1(v.w, h3, l3);
    *(__nv_bfloat162*)&g_decH[j * 4]     = make_bfloat162(h0, h1);
    *(__nv_bfloat162*)&g_decH[j * 4 + 2] = make_bfloat162(h2, h3);
    *(__nv_bfloat162*)&g_decL[j * 4]     = make_bfloat162(l0, l1);
    *(__nv_bfloat162*)&g_decL[j * 4 + 2] = make_bfloat162(l2, l3);
}

// enc: single read -> row-major split (encH/encL) + transposed split (encTH/encTL)
__global__ __launch_bounds__(256)
void split_enc_fused(const float* __restrict__ enc)
{
    __shared__ float ts[32][33];
    const int b = blockIdx.z;
    const int d0 = blockIdx.x * 32;
    const int e0 = blockIdx.y * 32;
    const int tx = threadIdx.x, ty = threadIdx.y;   // (32, 8)
    const float* src = enc + (size_t)b * EE * DDIM;
    __nv_bfloat16* rh = g_encH + (size_t)b * EE * DDIM;
    __nv_bfloat16* rl = g_encL + (size_t)b * EE * DDIM;
    #pragma unroll
    for (int j = 0; j < 4; j++) {
        const size_t o = (size_t)(e0 + ty + 8 * j) * DDIM + d0 + tx;
        float v = src[o];
        ts[ty + 8 * j][tx] = v;
        __nv_bfloat16 h, l; split1(v, h, l);
        rh[o] = h; rl[o] = l;
    }
    __syncthreads();
    __nv_bfloat16* oh = g_encTH + (size_t)b * DDIM * EE;
    __nv_bfloat16* ol = g_encTL + (size_t)b * DDIM * EE;
    #pragma unroll
    for (int j = 0; j < 4; j++) {
        float v = ts[tx][ty + 8 * j];
        __nv_bfloat16 h, l; split1(v, h, l);
        size_t o = (size_t)(d0 + ty + 8 * j) * EE + e0 + tx;
        oh[o] = h; ol[o] = l;
    }
}

// ---------------- combine 32 segments -> column max & inv-sum ---------------
__global__ __launch_bounds__(256)
void colstats_comb()
{
    const int i = blockIdx.x * 256 + threadIdx.x;   // over BB*EE
    const int b = i / EE, e = i % EE;
    float M = -1e30f;
    #pragma unroll
    for (int s = 0; s < NSEG; s++)
        M = fmaxf(M, g_mpart[((size_t)b * NSEG + s) * EE + e]);
    float S = 0.f;
    #pragma unroll
    for (int s = 0; s < NSEG; s++) {
        size_t idx = ((size_t)b * NSEG + s) * EE + e;
        S += g_spart[idx] * __expf(g_mpart[idx] - M);
    }
    g_colM[i] = M;
    g_colIS[i] = 1.0f / S;
}

// ---------------- normalize + split: scores -> PtH/PtL ----------------------
__global__ __launch_bounds__(256)
void softmax_split()
{
    size_t i = ((size_t)blockIdx.x * blockDim.x + threadIdx.x) * 4;  // [b][t][e]
    const int e = (int)(i % EE);
    const int b = (int)(i / ((size_t)TT * EE));
    float4 v = *(const float4*)&g_scores[i];
    float4 m4 = *(const float4*)&g_colM[b * EE + e];
    float4 s4 = *(const float4*)&g_colIS[b * EE + e];
    float p0 = __expf(v.x - m4.x) * s4.x;
    float p1 = __expf(v.y - m4.y) * s4.y;
    float p2 = __expf(v.z - m4.z) * s4.z;
    float p3 = __expf(v.w - m4.w) * s4.w;
    __nv_bfloat16 h0, h1, h2, h3, l0, l1, l2, l3;
    split1(p0, h0, l0); split1(p1, h1, l1); split1(p2, h2, l2); split1(p3, h3, l3);
    *(__nv_bfloat162*)&g_ptH[i]     = make_bfloat162(h0, h1);
    *(__nv_bfloat162*)&g_ptH[i + 2] = make_bfloat162(h2, h3);
    *(__nv_bfloat162*)&g_ptL[i]     = make_bfloat162(l0, l1);
    *(__nv_bfloat162*)&g_ptL[i + 2] = make_bfloat162(l2, l3);
}

// ---------------------------------------------------------------------------
extern "C" void kernel_launch(void* const* d_in, const int* in_sizes, int n_in,
                              void* d_out, int out_size)
{
    const float* enc = (const float*)d_in[0];
    const float* dec = (const float*)d_in[1];
    float* out = (float*)d_out;

    cudaFuncSetAttribute(gemm_bf16x3, cudaFuncAttributeMaxDynamicSharedMemorySize,
                         GEMM_SMEM);

    {
        dim3 g(DDIM / 32, EE / 32, BB);
        split_enc_fused<<<g, dim3(32, 8)>>>(enc);
    }
    split_dec<<<16384, 256>>>(dec);
    {
        dim3 g(EE / 128, TT / 128, BB);
        gemm_bf16x3<<<g, 256, GEMM_SMEM>>>(out, 0);
    }
    colstats_comb<<<BB * EE / 256, 256>>>();
    softmax_split<<<32768, 256>>>();
    {
        dim3 g(DDIM / 128, TT / 128, BB);
        gemm_bf16x3<<<g, 256, GEMM_SMEM>>>(out, 1);
    }
}